// round 2
// baseline (speedup 1.0000x reference)
#include <cuda_runtime.h>
#include <math.h>

// Problem constants (fixed-shape dataset)
#define N_IMG   32
#define M_FERN  16
#define KBITS   12
#define P_PAT   8
#define LP_BITS 3
#define D_DIM   64
#define HW      4096      // H*W = 64*64
#define TABLE   4096      // 2^K
#define PIX_PER_BLK 64
#define NTHREADS 256

// smem pool: mainloop needs 12*64 (T) + 64*8 (AT) + 64*8 (IT) = 1792 floats;
// epilogue transpose needs 64*65 = 4160 floats. Union -> 4160.
#define POOL_FLOATS (64*65)

__global__ __launch_bounds__(NTHREADS, 3)
void fern_sparse_kernel(const float* __restrict__ x,
                        const float* __restrict__ wt,
                        float* __restrict__ out)
{
    __shared__ float pool[POOL_FLOATS];
    float* Ts  = pool;                       // [12][64]  T values, k-major
    float* atb = pool + 12 * 64;             // [64][8]   activations
    int*   itb = (int*)(pool + 12*64 + 64*8);// [64][8]   table row offsets (pre-scaled)

    const int blk = blockIdx.x;
    const int n   = blk >> 6;                 // 64 blocks per image (4096/64)
    const int hw0 = (blk & 63) * PIX_PER_BLK;

    const int tid = threadIdx.x;
    const int dg  = tid & 15;                 // d-group: covers d = 4*dg .. 4*dg+3
    const int pg  = tid >> 4;                 // pixel group 0..15 (4 pixels each)

    float4 acc[4];
    #pragma unroll
    for (int i = 0; i < 4; i++) acc[i] = make_float4(0.f, 0.f, 0.f, 0.f);

    const float* xn = x + (size_t)n * (M_FERN * KBITS * HW) + hw0;

    for (int m = 0; m < M_FERN; m++) {
        // ---- stage T (12 channels x 64 pixels), coalesced ----
        #pragma unroll
        for (int i = tid; i < 12 * 64; i += NTHREADS) {
            int k = i >> 6;
            int p = i & 63;
            Ts[i] = xn[(size_t)(m * KBITS + k) * HW + p];
        }
        __syncthreads();

        // ---- per-pixel scalar phase: word pack + ambiguous bits + 8 patterns ----
        if (tid < PIX_PER_BLK) {
            float T[KBITS];
            #pragma unroll
            for (int k = 0; k < KBITS; k++) T[k] = Ts[k * 64 + tid];

            // MSB-first bit pack of round(T); rintf = round-half-to-even (matches jnp.round)
            int wb = 0;
            #pragma unroll
            for (int k = 0; k < KBITS; k++) wb = (wb << 1) | (int)rintf(T[k]);

            float ba[KBITS];
            #pragma unroll
            for (int k = 0; k < KBITS; k++) ba[k] = fabsf(T[k] - 0.5f);

            // 3x first-occurrence argmin (strict < matches jnp.argmin tie-break)
            int   ai[LP_BITS];
            float mv[LP_BITS];
            #pragma unroll
            for (int j = 0; j < LP_BITS; j++) {
                int best = 0; float bv = ba[0];
                #pragma unroll
                for (int k = 1; k < KBITS; k++) {
                    if (ba[k] < bv) { bv = ba[k]; best = k; }
                }
                ai[j] = best; mv[j] = T[best];
                ba[best] += 1.0f;   // exclude (matches BA + one_hot)
            }

            const int m0 = 1 << (11 - ai[0]);
            const int m1 = 1 << (11 - ai[1]);
            const int m2 = 1 << (11 - ai[2]);

            #pragma unroll
            for (int p = 0; p < P_PAT; p++) {
                float at = ((p & 1) ? mv[0] : 1.0f - mv[0])
                         * ((p & 2) ? mv[1] : 1.0f - mv[1])
                         * ((p & 4) ? mv[2] : 1.0f - mv[2]);
                int it = wb;
                it = (p & 1) ? (it | m0) : (it & ~m0);
                it = (p & 2) ? (it | m1) : (it & ~m1);
                it = (p & 4) ? (it | m2) : (it & ~m2);
                atb[tid * 8 + p] = at;
                itb[tid * 8 + p] = it * (D_DIM / 4);  // float4 row offset
            }
        }
        __syncthreads();

        // ---- gather + accumulate: 4 pixels x 8 patterns per thread, float4 ----
        const float4* __restrict__ Wm =
            (const float4*)(wt + (size_t)m * TABLE * D_DIM);
        #pragma unroll
        for (int i = 0; i < 4; i++) {
            const int pix = pg * 4 + i;
            #pragma unroll
            for (int p = 0; p < P_PAT; p++) {
                const float at  = atb[pix * 8 + p];
                const int   off = itb[pix * 8 + p];
                const float4 wv = Wm[off + dg];
                acc[i].x = fmaf(at, wv.x, acc[i].x);
                acc[i].y = fmaf(at, wv.y, acc[i].y);
                acc[i].z = fmaf(at, wv.z, acc[i].z);
                acc[i].w = fmaf(at, wv.w, acc[i].w);
            }
        }
        __syncthreads();  // before smem is overwritten (next fern / transpose)
    }

    // ---- epilogue: transpose to (d, pix) in smem, then coalesced store ----
    float* tr = pool;  // [64][65] padded
    #pragma unroll
    for (int i = 0; i < 4; i++) {
        const int pix = pg * 4 + i;
        tr[(4 * dg + 0) * 65 + pix] = acc[i].x;
        tr[(4 * dg + 1) * 65 + pix] = acc[i].y;
        tr[(4 * dg + 2) * 65 + pix] = acc[i].z;
        tr[(4 * dg + 3) * 65 + pix] = acc[i].w;
    }
    __syncthreads();

    float* outn = out + (size_t)n * (D_DIM * HW) + hw0;
    const int pixw = tid & 63;
    #pragma unroll
    for (int r = 0; r < 16; r++) {
        const int d = r * 4 + (tid >> 6);
        outn[(size_t)d * HW + pixw] = tr[d * 65 + pixw];
    }
}

extern "C" void kernel_launch(void* const* d_in, const int* in_sizes, int n_in,
                              void* d_out, int out_size)
{
    const float* x  = (const float*)d_in[0];
    const float* wt = (const float*)d_in[1];
    // defensive: x has 25,165,824 elems, weights 4,194,304
    if (n_in >= 2 && in_sizes[0] < in_sizes[1]) {
        const float* t = x; x = wt; wt = t;
    }
    float* out = (float*)d_out;

    const int blocks = N_IMG * (HW / PIX_PER_BLK);  // 2048
    fern_sparse_kernel<<<blocks, NTHREADS>>>(x, wt, out);
}

// round 4
// speedup vs baseline: 1.3373x; 1.3373x over previous
#include <cuda_runtime.h>
#include <cuda_fp16.h>
#include <math.h>

// Problem constants (fixed-shape dataset)
#define N_IMG   32
#define M_FERN  16
#define KBITS   12
#define P_PAT   8
#define LP_BITS 3
#define D_DIM   64
#define HW      4096      // H*W = 64*64
#define TABLE   4096      // 2^K
#define PIX_PER_BLK 64
#define NTHREADS 256

#define W_ELEMS (M_FERN * TABLE * D_DIM)   // 4,194,304

// fp16 copy of the weight table (8.4 MB scratch; device globals are allowed)
__device__ __half g_wt_h[W_ELEMS];

// ---- weights fp32 -> fp16 conversion (runs every launch; idempotent) ----
__global__ void convert_weights_kernel(const float* __restrict__ wt)
{
    int i = blockIdx.x * blockDim.x + threadIdx.x;   // half2 index
    const float2* src = (const float2*)wt;
    __half2* dst = (__half2*)g_wt_h;
    if (i < W_ELEMS / 2) dst[i] = __float22half2_rn(src[i]);
}

// smem pool: mainloop needs 12*64 (T) + 64*8 float2 (at,off) = 1792 floats;
// epilogue transpose needs 64*65 = 4160 floats. Union -> 4160.
#define POOL_FLOATS (64*65)

__global__ __launch_bounds__(NTHREADS, 4)
void fern_sparse_kernel(const float* __restrict__ x,
                        float* __restrict__ out)
{
    __shared__ float pool[POOL_FLOATS];
    float*  Ts = pool;                         // [12][64]  T values, k-major
    float2* ap = (float2*)(pool + 12 * 64);    // [64][8]   {activation, offset-as-int}

    const int blk = blockIdx.x;
    const int n   = blk >> 6;                  // 64 blocks per image (4096/64)
    const int hw0 = (blk & 63) * PIX_PER_BLK;

    const int tid = threadIdx.x;
    const int dg  = tid & 15;                  // d-group: covers d = 4*dg .. 4*dg+3
    const int pg  = tid >> 4;                  // pixel group 0..15 (4 pixels each)

    float4 acc[4];
    #pragma unroll
    for (int i = 0; i < 4; i++) acc[i] = make_float4(0.f, 0.f, 0.f, 0.f);

    const float* xn = x + (size_t)n * (M_FERN * KBITS * HW) + hw0;

    for (int m = 0; m < M_FERN; m++) {
        // ---- stage T (12 channels x 64 pixels), coalesced ----
        #pragma unroll
        for (int i = tid; i < 12 * 64; i += NTHREADS) {
            int k = i >> 6;
            int p = i & 63;
            Ts[i] = xn[(size_t)(m * KBITS + k) * HW + p];
        }
        __syncthreads();

        // ---- per-pixel scalar phase: word pack + ambiguous bits + 8 patterns ----
        if (tid < PIX_PER_BLK) {
            float T[KBITS];
            #pragma unroll
            for (int k = 0; k < KBITS; k++) T[k] = Ts[k * 64 + tid];

            // MSB-first bit pack of round(T); rintf = round-half-to-even (matches jnp.round)
            int wb = 0;
            #pragma unroll
            for (int k = 0; k < KBITS; k++) wb = (wb << 1) | (int)rintf(T[k]);

            float ba[KBITS];
            #pragma unroll
            for (int k = 0; k < KBITS; k++) ba[k] = fabsf(T[k] - 0.5f);

            // 3x first-occurrence argmin (strict < matches jnp.argmin tie-break)
            int   ai[LP_BITS];
            float mv[LP_BITS];
            #pragma unroll
            for (int j = 0; j < LP_BITS; j++) {
                int best = 0; float bv = ba[0];
                #pragma unroll
                for (int k = 1; k < KBITS; k++) {
                    if (ba[k] < bv) { bv = ba[k]; best = k; }
                }
                ai[j] = best; mv[j] = T[best];
                ba[best] += 1.0f;   // exclude (matches BA + one_hot)
            }

            const int m0 = 1 << (11 - ai[0]);
            const int m1 = 1 << (11 - ai[1]);
            const int m2 = 1 << (11 - ai[2]);

            #pragma unroll
            for (int p = 0; p < P_PAT; p++) {
                float at = ((p & 1) ? mv[0] : 1.0f - mv[0])
                         * ((p & 2) ? mv[1] : 1.0f - mv[1])
                         * ((p & 4) ? mv[2] : 1.0f - mv[2]);
                int it = wb;
                it = (p & 1) ? (it | m0) : (it & ~m0);
                it = (p & 2) ? (it | m1) : (it & ~m1);
                it = (p & 4) ? (it | m2) : (it & ~m2);
                float2 v;
                v.x = at;
                v.y = __int_as_float(it * (D_DIM / 4));  // uint2 row offset (16 per row)
                ap[tid * 8 + p] = v;
            }
        }
        __syncthreads();

        // ---- gather + accumulate: 4 pixels x 8 patterns per thread ----
        // fp16 row = 128 B -> one cache line per (pixel, pattern); each lane
        // loads 8 B (4 halves) -> 16 consecutive lanes cover the line.
        const uint2* __restrict__ Wm =
            (const uint2*)(g_wt_h + (size_t)m * TABLE * D_DIM);
        #pragma unroll
        for (int i = 0; i < 4; i++) {
            const int pix = pg * 4 + i;
            #pragma unroll
            for (int p = 0; p < P_PAT; p++) {
                const float2 v  = ap[pix * 8 + p];
                const float  at = v.x;
                const int    off = __float_as_int(v.y);
                const uint2  wv = Wm[off + dg];
                const float2 f0 = __half22float2(*(const __half2*)&wv.x);
                const float2 f1 = __half22float2(*(const __half2*)&wv.y);
                acc[i].x = fmaf(at, f0.x, acc[i].x);
                acc[i].y = fmaf(at, f0.y, acc[i].y);
                acc[i].z = fmaf(at, f1.x, acc[i].z);
                acc[i].w = fmaf(at, f1.y, acc[i].w);
            }
        }
        __syncthreads();  // before smem is overwritten (next fern / transpose)
    }

    // ---- epilogue: transpose to (d, pix) in smem, then coalesced store ----
    float* tr = pool;  // [64][65] padded
    #pragma unroll
    for (int i = 0; i < 4; i++) {
        const int pix = pg * 4 + i;
        tr[(4 * dg + 0) * 65 + pix] = acc[i].x;
        tr[(4 * dg + 1) * 65 + pix] = acc[i].y;
        tr[(4 * dg + 2) * 65 + pix] = acc[i].z;
        tr[(4 * dg + 3) * 65 + pix] = acc[i].w;
    }
    __syncthreads();

    float* outn = out + (size_t)n * (D_DIM * HW) + hw0;
    const int pixw = tid & 63;
    #pragma unroll
    for (int r = 0; r < 16; r++) {
        const int d = r * 4 + (tid >> 6);
        outn[(size_t)d * HW + pixw] = tr[d * 65 + pixw];
    }
}

extern "C" void kernel_launch(void* const* d_in, const int* in_sizes, int n_in,
                              void* d_out, int out_size)
{
    const float* x  = (const float*)d_in[0];
    const float* wt = (const float*)d_in[1];
    // defensive: x has 25,165,824 elems, weights 4,194,304
    if (n_in >= 2 && in_sizes[0] < in_sizes[1]) {
        const float* t = x; x = wt; wt = t;
    }
    float* out = (float*)d_out;

    // 1) convert weights to fp16 scratch (stream-ordered before main kernel)
    convert_weights_kernel<<<(W_ELEMS / 2 + 255) / 256, 256>>>(wt);

    // 2) main kernel
    const int blocks = N_IMG * (HW / PIX_PER_BLK);  // 2048
    fern_sparse_kernel<<<blocks, NTHREADS>>>(x, out);
}